// round 3
// baseline (speedup 1.0000x reference)
#include <cuda_runtime.h>
#include <cuda_bf16.h>
#include <cstdint>

#define Bb   8
#define Nn   1024
#define Hh   8
#define Dd   128
#define ROWS (Bb*Nn)      // 8192
#define EPSc 1e-5f

// ---------------- scratch (static; no cudaMalloc) ---------------------------
__device__ float              g_Wt[Dd*Dd];
__device__ float              g_Wh[ROWS*Dd];
__device__ float4             g_q[Bb*Hh*Nn];   // {s_i, e^{s_i}, e^{0.2 s_i}, 0}
__device__ float4             g_k[Bb*Hh*Nn];
__device__ unsigned long long g_maskbits[(size_t)ROWS*Nn/64];
__device__ float              g_hcat[ROWS*Dd];
__device__ float              g_x[ROWS*Dd];
__device__ float              g_y[ROWS*2*Dd];

// ---------------- helpers ---------------------------------------------------
__device__ __forceinline__ unsigned long long pack2(float x) {
    unsigned long long r;
    asm("mov.b64 %0, {%1, %1};" : "=l"(r) : "f"(x));
    return r;
}
__device__ __forceinline__ void fma2(unsigned long long& acc, unsigned long long ab,
                                     unsigned long long c) {
    asm("fma.rn.f32x2 %0, %1, %2, %0;" : "+l"(acc) : "l"(ab), "l"(c));
}
union F4U { float4 f4; unsigned long long u[2]; };

// ---------------- 1. pack adjacency mask ------------------------------------
__global__ __launch_bounds__(1024) void pack_mask_kernel(const int* __restrict__ adj) {
    int tid = blockIdx.x * blockDim.x + threadIdx.x;
    int v = adj[tid];
    unsigned bal = __ballot_sync(0xffffffffu, v != 0);
    if ((threadIdx.x & 31) == 0)
        ((unsigned*)g_maskbits)[tid >> 5] = bal;
}

// ---------------- 2. reorder W (H,IN,HD) -> Wt (IN, H*HD) -------------------
__global__ void transpose_w_kernel(const float* __restrict__ W) {
    int tid = blockIdx.x * blockDim.x + threadIdx.x;
    int i = tid >> 7;
    int o = tid & 127;
    int h = o >> 4, d = o & 15;
    g_Wt[tid] = W[(h << 11) + (i << 4) + d];
}

// ---------------- fused 64x128-tile SGEMM, 3 modes --------------------------
// MODE 0: C=Wh = A@B, epilogue computes per-(b,h,n) score exp tables -> g_q/g_k
// MODE 1: C = relu(A@B + bias)                    (N may be 256, col-tiled)
// MODE 2: C = LayerNorm(extra + A@B + bias)*gam+bet   (full-row tile, N=128)
template<int MODE>
__global__ __launch_bounds__(256) void gemm_kernel(
        const float* __restrict__ A, const float* __restrict__ Bm,
        const float* __restrict__ bias, const float* __restrict__ extra,
        const float* __restrict__ gam, const float* __restrict__ bet,
        float* __restrict__ C, int K, int N) {
    __shared__ float As[16][68];
    __shared__ float Bs[16][128];
    __shared__ float sa_src[128], sa_dst[128];
    int t  = threadIdx.x;
    int tx = t & 15, ty = t >> 4;
    int row0 = blockIdx.y * 64;
    int col0 = blockIdx.x * 128;

    if (MODE == 0 && t < 128) {
        int hh = t >> 4, d = t & 15;
        sa_src[t] = extra[hh * 32 + d];
        sa_dst[t] = extra[hh * 32 + 16 + d];
    }

    float acc[4][8];
#pragma unroll
    for (int i = 0; i < 4; i++)
#pragma unroll
        for (int j = 0; j < 8; j++) acc[i][j] = 0.f;

    int arow = t >> 2, ak = (t & 3) << 2;
    for (int k0 = 0; k0 < K; k0 += 16) {
        float4 av = *(const float4*)&A[(size_t)(row0 + arow) * K + k0 + ak];
        int brow0 = t >> 5, bcol = (t & 31) << 2;
        float4 b0 = *(const float4*)&Bm[(size_t)(k0 + brow0) * N + col0 + bcol];
        float4 b1 = *(const float4*)&Bm[(size_t)(k0 + brow0 + 8) * N + col0 + bcol];
        __syncthreads();
        As[ak + 0][arow] = av.x; As[ak + 1][arow] = av.y;
        As[ak + 2][arow] = av.z; As[ak + 3][arow] = av.w;
        *(float4*)&Bs[brow0][bcol]     = b0;
        *(float4*)&Bs[brow0 + 8][bcol] = b1;
        __syncthreads();
#pragma unroll
        for (int k = 0; k < 16; k++) {
            float4 a4 = *(const float4*)&As[k][ty << 2];
            float4 q0 = *(const float4*)&Bs[k][tx << 3];
            float4 q1 = *(const float4*)&Bs[k][(tx << 3) + 4];
            float bvv[8] = {q0.x, q0.y, q0.z, q0.w, q1.x, q1.y, q1.z, q1.w};
            float avv[4] = {a4.x, a4.y, a4.z, a4.w};
#pragma unroll
            for (int i = 0; i < 4; i++)
#pragma unroll
                for (int j = 0; j < 8; j++) acc[i][j] += avv[i] * bvv[j];
        }
    }

    if (MODE == 0) {
#pragma unroll
        for (int i = 0; i < 4; i++) {
            int r = row0 + (ty << 2) + i;
            *(float4*)&C[(size_t)r * 128 + (tx << 3)] =
                make_float4(acc[i][0], acc[i][1], acc[i][2], acc[i][3]);
            *(float4*)&C[(size_t)r * 128 + (tx << 3) + 4] =
                make_float4(acc[i][4], acc[i][5], acc[i][6], acc[i][7]);
            float sp = 0.f, dp = 0.f;
#pragma unroll
            for (int j = 0; j < 8; j++) {
                sp += acc[i][j] * sa_src[(tx << 3) + j];
                dp += acc[i][j] * sa_dst[(tx << 3) + j];
            }
            sp += __shfl_xor_sync(0xffffffffu, sp, 1);
            dp += __shfl_xor_sync(0xffffffffu, dp, 1);
            if (!(tx & 1)) {
                int b = r >> 10, n = r & 1023;
                int hh = tx >> 1;
                int idx = ((b << 3) + hh) * 1024 + n;
                g_q[idx] = make_float4(sp, __expf(sp), __expf(0.2f * sp), 0.f);
                g_k[idx] = make_float4(dp, __expf(dp), __expf(0.2f * dp), 0.f);
            }
        }
    } else if (MODE == 1) {
        float bv[8];
#pragma unroll
        for (int j = 0; j < 8; j++) bv[j] = bias[col0 + (tx << 3) + j];
#pragma unroll
        for (int i = 0; i < 4; i++) {
            int r = row0 + (ty << 2) + i;
            float4 r0, r1;
            r0.x = fmaxf(acc[i][0] + bv[0], 0.f); r0.y = fmaxf(acc[i][1] + bv[1], 0.f);
            r0.z = fmaxf(acc[i][2] + bv[2], 0.f); r0.w = fmaxf(acc[i][3] + bv[3], 0.f);
            r1.x = fmaxf(acc[i][4] + bv[4], 0.f); r1.y = fmaxf(acc[i][5] + bv[5], 0.f);
            r1.z = fmaxf(acc[i][6] + bv[6], 0.f); r1.w = fmaxf(acc[i][7] + bv[7], 0.f);
            *(float4*)&C[(size_t)r * N + col0 + (tx << 3)]     = r0;
            *(float4*)&C[(size_t)r * N + col0 + (tx << 3) + 4] = r1;
        }
    } else {                       // MODE 2: residual + LN
        float bv[8], gv[8], bb[8];
#pragma unroll
        for (int j = 0; j < 8; j++) {
            bv[j] = bias[(tx << 3) + j];
            gv[j] = gam[(tx << 3) + j];
            bb[j] = bet[(tx << 3) + j];
        }
#pragma unroll
        for (int i = 0; i < 4; i++) {
            int r = row0 + (ty << 2) + i;
            float4 x0 = *(const float4*)&extra[(size_t)r * 128 + (tx << 3)];
            float4 x1 = *(const float4*)&extra[(size_t)r * 128 + (tx << 3) + 4];
            float v[8] = {x0.x, x0.y, x0.z, x0.w, x1.x, x1.y, x1.z, x1.w};
            float s = 0.f, s2 = 0.f;
#pragma unroll
            for (int j = 0; j < 8; j++) {
                v[j] += acc[i][j] + bv[j];
                s += v[j]; s2 += v[j] * v[j];
            }
#pragma unroll
            for (int o = 1; o <= 8; o <<= 1) {
                s  += __shfl_xor_sync(0xffffffffu, s,  o);
                s2 += __shfl_xor_sync(0xffffffffu, s2, o);
            }
            float mu  = s * (1.f / 128.f);
            float var = s2 * (1.f / 128.f) - mu * mu;
            float rs  = rsqrtf(var + EPSc);
            float4 r0, r1;
            r0.x = (v[0]-mu)*rs*gv[0]+bb[0]; r0.y = (v[1]-mu)*rs*gv[1]+bb[1];
            r0.z = (v[2]-mu)*rs*gv[2]+bb[2]; r0.w = (v[3]-mu)*rs*gv[3]+bb[3];
            r1.x = (v[4]-mu)*rs*gv[4]+bb[4]; r1.y = (v[5]-mu)*rs*gv[5]+bb[5];
            r1.z = (v[6]-mu)*rs*gv[6]+bb[6]; r1.w = (v[7]-mu)*rs*gv[7]+bb[7];
            *(float4*)&C[(size_t)r * 128 + (tx << 3)]     = r0;
            *(float4*)&C[(size_t)r * 128 + (tx << 3) + 4] = r1;
        }
    }
}

// ---------------- fused masked-softmax attention ----------------------------
// grid (N/64, H, B), 128 threads. thread t: n = bx*64 + (t>>1), half = t&1.
// Each half processes 512 of the 1024 m's; halves combined by shfl at the end.
__global__ __launch_bounds__(128) void att_kernel() {
    int b = blockIdx.z, hh = blockIdx.y;
    int t = threadIdx.x;
    int half = t & 1;
    int n = blockIdx.x * 64 + (t >> 1);

    __shared__ float4 sk4[128];
    __shared__ float4 swh[128][4];

    int bhN = (b * Hh + hh) * Nn;
    int bN  = b * Nn;
    float4 q = g_q[bhN + n];
    float s_i = q.x, E1 = q.y, E2 = q.z;

    unsigned long long acc[8];
#pragma unroll
    for (int j = 0; j < 8; j++) acc[j] = 0ULL;
    float sumw = 0.f;

    const unsigned long long* mrow = g_maskbits + (size_t)(bN + n) * (Nn / 64);
    int base = half << 6;

    for (int it = 0; it < 8; it++) {
        __syncthreads();
        {   // rows 0..63 <- m = it*64+r (half 0's range), rows 64..127 <- m = 512+it*64+(r-64)
            int r = t;
            int msrc = (r < 64) ? (it * 64 + r) : (448 + it * 64 + r);
            sk4[r] = g_k[bhN + msrc];
#pragma unroll
            for (int jj = 0; jj < 4; jj++) {
                int fi = t + (jj << 7);
                int mi = fi >> 2, q4 = fi & 3;
                int mm = (mi < 64) ? (it * 64 + mi) : (448 + it * 64 + mi);
                swh[mi][q4] =
                    *(const float4*)&g_Wh[(size_t)(bN + mm) * Dd + (hh << 4) + (q4 << 2)];
            }
        }
        __syncthreads();

        unsigned long long bits = mrow[(half << 3) + it];
#pragma unroll 8
        for (int k = 0; k < 64; k++) {
            float4 k4 = sk4[base + k];
            float ts = s_i + k4.x;
            float w = (ts >= 0.f) ? (E1 * k4.y) : (E2 * k4.z);
            if (!((bits >> k) & 1ULL)) w = 0.f;
            sumw += w;
            unsigned long long w2 = pack2(w);
            F4U w0, w1, w2r, w3;
            w0.f4 = swh[base + k][0]; w1.f4 = swh[base + k][1];
            w2r.f4 = swh[base + k][2]; w3.f4 = swh[base + k][3];
            fma2(acc[0], w2, w0.u[0]); fma2(acc[1], w2, w0.u[1]);
            fma2(acc[2], w2, w1.u[0]); fma2(acc[3], w2, w1.u[1]);
            fma2(acc[4], w2, w2r.u[0]); fma2(acc[5], w2, w2r.u[1]);
            fma2(acc[6], w2, w3.u[0]); fma2(acc[7], w2, w3.u[1]);
        }
    }

    // combine the two halves (lanes 2k / 2k+1)
#pragma unroll
    for (int j = 0; j < 8; j++) {
        unsigned long long o = __shfl_xor_sync(0xffffffffu, acc[j], 1);
        float2 m = *(float2*)&acc[j];
        float2 p = *(float2*)&o;
        m.x += p.x; m.y += p.y;
        *(float2*)&acc[j] = m;
    }
    sumw += __shfl_xor_sync(0xffffffffu, sumw, 1);
    float inv = (sumw > 0.f) ? __fdividef(1.f, sumw) : 0.f;

    float2* dst = (float2*)&g_hcat[(size_t)(bN + n) * Dd + (hh << 4)];
#pragma unroll
    for (int jj = 0; jj < 4; jj++) {
        int j = (half << 2) + jj;
        float2 v = *(float2*)&acc[j];
        v.x *= inv; v.y *= inv;
        dst[j] = v;
    }
}

// ---------------- LN1 (residual + layernorm) --------------------------------
__global__ __launch_bounds__(128) void ln_kernel(
        const float* __restrict__ A, const float* __restrict__ R,
        const float* __restrict__ g, const float* __restrict__ bta,
        float* __restrict__ out) {
    int row = blockIdx.x;
    int c = threadIdx.x;
    size_t basei = (size_t)row * Dd;
    float v = A[basei + c] + R[basei + c];
    float s = v, s2 = v * v;
#pragma unroll
    for (int o = 16; o > 0; o >>= 1) {
        s  += __shfl_xor_sync(0xffffffffu, s,  o);
        s2 += __shfl_xor_sync(0xffffffffu, s2, o);
    }
    __shared__ float ws[4], ws2[4];
    int w = threadIdx.x >> 5;
    if ((threadIdx.x & 31) == 0) { ws[w] = s; ws2[w] = s2; }
    __syncthreads();
    s  = ws[0]  + ws[1]  + ws[2]  + ws[3];
    s2 = ws2[0] + ws2[1] + ws2[2] + ws2[3];
    float mu  = s * (1.f / Dd);
    float var = s2 * (1.f / Dd) - mu * mu;
    float r = rsqrtf(var + EPSc);
    out[basei + c] = (v - mu) * r * g[c] + bta[c];
}

// ---------------- launch ----------------------------------------------------
extern "C" void kernel_launch(void* const* d_in, const int* in_sizes, int n_in,
                              void* d_out, int out_size) {
    const float* h    = (const float*)d_in[0];
    const int*   adj  = (const int*)d_in[1];
    const float* W    = (const float*)d_in[2];
    const float* a    = (const float*)d_in[3];
    const float* ln1g = (const float*)d_in[4];
    const float* ln1b = (const float*)d_in[5];
    const float* w1   = (const float*)d_in[6];
    const float* b1   = (const float*)d_in[7];
    const float* w2   = (const float*)d_in[8];
    const float* b2   = (const float*)d_in[9];
    const float* ln2g = (const float*)d_in[10];
    const float* ln2b = (const float*)d_in[11];
    float* out = (float*)d_out;

    float *Wt, *Wh, *hcat, *x, *y;
    cudaGetSymbolAddress((void**)&Wt,   g_Wt);
    cudaGetSymbolAddress((void**)&Wh,   g_Wh);
    cudaGetSymbolAddress((void**)&hcat, g_hcat);
    cudaGetSymbolAddress((void**)&x,    g_x);
    cudaGetSymbolAddress((void**)&y,    g_y);

    pack_mask_kernel<<<(Bb * Nn * Nn) / 1024, 1024>>>(adj);
    transpose_w_kernel<<<(Dd * Dd) / 1024, 1024>>>(W);
    // Wh + score/exp tables (fused)
    gemm_kernel<0><<<dim3(1, ROWS / 64), 256>>>(h, Wt, nullptr, a, nullptr, nullptr,
                                                Wh, Dd, Dd);
    // attention
    att_kernel<<<dim3(Nn / 64, Hh, Bb), 128>>>();
    // LN1(hcat + h) -> x
    ln_kernel<<<ROWS, Dd>>>(hcat, h, ln1g, ln1b, x);
    // y = relu(x @ w1 + b1)
    gemm_kernel<1><<<dim3(2, ROWS / 64), 256>>>(x, w1, b1, nullptr, nullptr, nullptr,
                                                y, Dd, 2 * Dd);
    // out = LN2(x + y @ w2 + b2)   (fully fused epilogue)
    gemm_kernel<2><<<dim3(1, ROWS / 64), 256>>>(y, w2, b2, x, ln2g, ln2b,
                                                out, 2 * Dd, Dd);
}

// round 4
// speedup vs baseline: 1.4997x; 1.4997x over previous
#include <cuda_runtime.h>
#include <cuda_bf16.h>
#include <cstdint>

#define Bb   8
#define Nn   1024
#define Hh   8
#define Dd   128
#define ROWS (Bb*Nn)      // 8192
#define EPSc 1e-5f

typedef unsigned long long ull;

// ---------------- scratch (static; no cudaMalloc) ---------------------------
__device__ float  g_Wt[Dd*Dd];
__device__ float  g_Wh[ROWS*Dd];
__device__ float4 g_q[Bb*Hh*Nn];   // {s_i, e^{s_i}, e^{0.2 s_i}, 0}
__device__ float4 g_k[Bb*Hh*Nn];
__device__ ull    g_maskbits[(size_t)ROWS*Nn/64];
__device__ float  g_hcat[ROWS*Dd];
__device__ float  g_x[ROWS*Dd];
__device__ float  g_y[ROWS*2*Dd];

// ---------------- helpers ---------------------------------------------------
__device__ __forceinline__ ull pack2(float x) {
    ull r;
    asm("mov.b64 %0, {%1, %1};" : "=l"(r) : "f"(x));
    return r;
}
__device__ __forceinline__ void fma2(ull& acc, ull ab, ull c) {
    asm("fma.rn.f32x2 %0, %1, %2, %0;" : "+l"(acc) : "l"(ab), "l"(c));
}
union F4U { float4 f4; ull u[2]; float f[4]; };

// ---------------- 1. pack adjacency mask (int4 + nibble compose) ------------
__global__ __launch_bounds__(256) void pack_mask_kernel(const int4* __restrict__ adj4) {
    __shared__ unsigned char nib[256];
    int t = threadIdx.x;
    int4 v = adj4[(size_t)blockIdx.x * 256 + t];
    unsigned n = (v.x != 0) | ((v.y != 0) << 1) | ((v.z != 0) << 2) | ((v.w != 0) << 3);
    nib[t] = (unsigned char)n;
    __syncthreads();
    if (t < 16) {
        uint4 bytes = *(const uint4*)(nib + t * 16);
        unsigned w[4] = {bytes.x, bytes.y, bytes.z, bytes.w};
        ull word = 0;
#pragma unroll
        for (int i = 0; i < 4; i++) {
            unsigned x = w[i];
            unsigned o = (x & 0xFu) | ((x >> 4) & 0xF0u) |
                         ((x >> 8) & 0xF00u) | ((x >> 12) & 0xF000u);
            word |= (ull)o << (16 * i);
        }
        g_maskbits[(size_t)blockIdx.x * 16 + t] = word;
    }
}

// ---------------- 2. reorder W (H,IN,HD) -> Wt (IN, H*HD) -------------------
__global__ void transpose_w_kernel(const float* __restrict__ W) {
    int tid = blockIdx.x * blockDim.x + threadIdx.x;
    int i = tid >> 7;
    int o = tid & 127;
    int h = o >> 4, d = o & 15;
    g_Wt[tid] = W[(h << 11) + (i << 4) + d];
}

// ---------------- fused 64x128-tile SGEMM (f32x2 core), 3 modes -------------
// MODE 0: C=Wh = A@B, epilogue -> score exp tables g_q/g_k
// MODE 1: C = relu(A@B + bias)
// MODE 2: C = LayerNorm(extra + A@B + bias)*gam+bet
template<int MODE>
__global__ __launch_bounds__(256) void gemm_kernel(
        const float* __restrict__ A, const float* __restrict__ Bm,
        const float* __restrict__ bias, const float* __restrict__ extra,
        const float* __restrict__ gam, const float* __restrict__ bet,
        float* __restrict__ C, int K, int N) {
    __shared__ float As[16][68];
    __shared__ float Bs[16][128];
    __shared__ float sa_src[128], sa_dst[128];
    int t  = threadIdx.x;
    int tx = t & 15, ty = t >> 4;
    int row0 = blockIdx.y * 64;
    int col0 = blockIdx.x * 128;

    if (MODE == 0 && t < 128) {
        int hh = t >> 4, d = t & 15;
        sa_src[t] = extra[hh * 32 + d];
        sa_dst[t] = extra[hh * 32 + 16 + d];
    }

    ull acc2[4][4];
#pragma unroll
    for (int i = 0; i < 4; i++)
#pragma unroll
        for (int j = 0; j < 4; j++) acc2[i][j] = 0ULL;

    int arow = t >> 2, ak = (t & 3) << 2;
    for (int k0 = 0; k0 < K; k0 += 16) {
        float4 av = *(const float4*)&A[(size_t)(row0 + arow) * K + k0 + ak];
        int brow0 = t >> 5, bcol = (t & 31) << 2;
        float4 b0 = *(const float4*)&Bm[(size_t)(k0 + brow0) * N + col0 + bcol];
        float4 b1 = *(const float4*)&Bm[(size_t)(k0 + brow0 + 8) * N + col0 + bcol];
        __syncthreads();
        As[ak + 0][arow] = av.x; As[ak + 1][arow] = av.y;
        As[ak + 2][arow] = av.z; As[ak + 3][arow] = av.w;
        *(float4*)&Bs[brow0][bcol]     = b0;
        *(float4*)&Bs[brow0 + 8][bcol] = b1;
        __syncthreads();
#pragma unroll
        for (int k = 0; k < 16; k++) {
            float4 a4 = *(const float4*)&As[k][ty << 2];
            F4U q0, q1;
            q0.f4 = *(const float4*)&Bs[k][tx << 3];
            q1.f4 = *(const float4*)&Bs[k][(tx << 3) + 4];
            ull bp[4] = {q0.u[0], q0.u[1], q1.u[0], q1.u[1]};
            ull ap[4] = {pack2(a4.x), pack2(a4.y), pack2(a4.z), pack2(a4.w)};
#pragma unroll
            for (int i = 0; i < 4; i++)
#pragma unroll
                for (int j = 0; j < 4; j++) fma2(acc2[i][j], ap[i], bp[j]);
        }
    }

    // unpack accumulators to floats
    float acc[4][8];
#pragma unroll
    for (int i = 0; i < 4; i++)
#pragma unroll
        for (int j = 0; j < 4; j++) {
            float2 p = *(float2*)&acc2[i][j];
            acc[i][2 * j]     = p.x;
            acc[i][2 * j + 1] = p.y;
        }

    if (MODE == 0) {
#pragma unroll
        for (int i = 0; i < 4; i++) {
            int r = row0 + (ty << 2) + i;
            *(float4*)&C[(size_t)r * 128 + (tx << 3)] =
                make_float4(acc[i][0], acc[i][1], acc[i][2], acc[i][3]);
            *(float4*)&C[(size_t)r * 128 + (tx << 3) + 4] =
                make_float4(acc[i][4], acc[i][5], acc[i][6], acc[i][7]);
            float sp = 0.f, dp = 0.f;
#pragma unroll
            for (int j = 0; j < 8; j++) {
                sp += acc[i][j] * sa_src[(tx << 3) + j];
                dp += acc[i][j] * sa_dst[(tx << 3) + j];
            }
            sp += __shfl_xor_sync(0xffffffffu, sp, 1);
            dp += __shfl_xor_sync(0xffffffffu, dp, 1);
            if (!(tx & 1)) {
                int b = r >> 10, n = r & 1023;
                int hh = tx >> 1;
                int idx = ((b << 3) + hh) * 1024 + n;
                g_q[idx] = make_float4(sp, __expf(sp), __expf(0.2f * sp), 0.f);
                g_k[idx] = make_float4(dp, __expf(dp), __expf(0.2f * dp), 0.f);
            }
        }
    } else if (MODE == 1) {
        float bv[8];
#pragma unroll
        for (int j = 0; j < 8; j++) bv[j] = bias[col0 + (tx << 3) + j];
#pragma unroll
        for (int i = 0; i < 4; i++) {
            int r = row0 + (ty << 2) + i;
            float4 r0, r1;
            r0.x = fmaxf(acc[i][0] + bv[0], 0.f); r0.y = fmaxf(acc[i][1] + bv[1], 0.f);
            r0.z = fmaxf(acc[i][2] + bv[2], 0.f); r0.w = fmaxf(acc[i][3] + bv[3], 0.f);
            r1.x = fmaxf(acc[i][4] + bv[4], 0.f); r1.y = fmaxf(acc[i][5] + bv[5], 0.f);
            r1.z = fmaxf(acc[i][6] + bv[6], 0.f); r1.w = fmaxf(acc[i][7] + bv[7], 0.f);
            *(float4*)&C[(size_t)r * N + col0 + (tx << 3)]     = r0;
            *(float4*)&C[(size_t)r * N + col0 + (tx << 3) + 4] = r1;
        }
    } else {
        float bv[8], gv[8], bb[8];
#pragma unroll
        for (int j = 0; j < 8; j++) {
            bv[j] = bias[(tx << 3) + j];
            gv[j] = gam[(tx << 3) + j];
            bb[j] = bet[(tx << 3) + j];
        }
#pragma unroll
        for (int i = 0; i < 4; i++) {
            int r = row0 + (ty << 2) + i;
            float4 x0 = *(const float4*)&extra[(size_t)r * 128 + (tx << 3)];
            float4 x1 = *(const float4*)&extra[(size_t)r * 128 + (tx << 3) + 4];
            float v[8] = {x0.x, x0.y, x0.z, x0.w, x1.x, x1.y, x1.z, x1.w};
            float s = 0.f, s2 = 0.f;
#pragma unroll
            for (int j = 0; j < 8; j++) {
                v[j] += acc[i][j] + bv[j];
                s += v[j]; s2 += v[j] * v[j];
            }
#pragma unroll
            for (int o = 1; o <= 8; o <<= 1) {
                s  += __shfl_xor_sync(0xffffffffu, s,  o);
                s2 += __shfl_xor_sync(0xffffffffu, s2, o);
            }
            float mu  = s * (1.f / 128.f);
            float var = s2 * (1.f / 128.f) - mu * mu;
            float rs  = rsqrtf(var + EPSc);
            float4 r0, r1;
            r0.x = (v[0]-mu)*rs*gv[0]+bb[0]; r0.y = (v[1]-mu)*rs*gv[1]+bb[1];
            r0.z = (v[2]-mu)*rs*gv[2]+bb[2]; r0.w = (v[3]-mu)*rs*gv[3]+bb[3];
            r1.x = (v[4]-mu)*rs*gv[4]+bb[4]; r1.y = (v[5]-mu)*rs*gv[5]+bb[5];
            r1.z = (v[6]-mu)*rs*gv[6]+bb[6]; r1.w = (v[7]-mu)*rs*gv[7]+bb[7];
            *(float4*)&C[(size_t)r * 128 + (tx << 3)]     = r0;
            *(float4*)&C[(size_t)r * 128 + (tx << 3) + 4] = r1;
        }
    }
}

// ---------------- fused masked-softmax attention (4 queries / thread) -------
// grid (8, H, B), block 128. Lane l: ms = l&3 (m-split), qg = l>>2.
// Thread handles queries qbase..qbase+3 over m in [ms*256, ms*256+256).
// Staged smem row (80B): [16 Wh floats][s_j, e^sj, e^.2sj, pad].
__global__ __launch_bounds__(128, 4) void att_kernel() {
    __shared__ float sbuf[256 * 20];   // 20 KB
    int b = blockIdx.z, hh = blockIdx.y;
    int t = threadIdx.x;
    int l = t & 31, wp = t >> 5;
    int ms = l & 3;
    int qbase = blockIdx.x * 128 + ((wp << 3) + (l >> 2)) << 0;
    qbase = blockIdx.x * 128 + ((wp << 3) + (l >> 2)) * 4;
    int bN = b * Nn, bhN = (b * Hh + hh) * Nn;

    float si[4], E1[4], E2[4];
#pragma unroll
    for (int q = 0; q < 4; q++) {
        float4 qq = g_q[bhN + qbase + q];
        si[q] = qq.x; E1[q] = qq.y; E2[q] = qq.z;
    }
    const ull* mbase = g_maskbits + (size_t)(bN + qbase) * 16;

    ull acc[4][8];
#pragma unroll
    for (int q = 0; q < 4; q++)
#pragma unroll
        for (int j = 0; j < 8; j++) acc[q][j] = 0ULL;
    float sumw[4] = {0.f, 0.f, 0.f, 0.f};

    for (int s = 0; s < 4; s++) {
        __syncthreads();
        // stage Wh rows: row r = kk*4 + chunk  <-  m = chunk*256 + s*64 + kk
#pragma unroll
        for (int u = 0; u < 8; u++) {
            int fi = u * 128 + t;             // 0..1023 (m-local, j)
            int ml = fi >> 2, j = fi & 3;
            int chunk = ml >> 6, kk = ml & 63;
            int m = chunk * 256 + s * 64 + kk;
            float4 v = *(const float4*)&g_Wh[(size_t)(bN + m) * 128 + (hh << 4) + (j << 2)];
            *(float4*)&sbuf[(kk * 4 + chunk) * 20 + (j << 2)] = v;
        }
#pragma unroll
        for (int u = 0; u < 2; u++) {
            int ml = u * 128 + t;
            int chunk = ml >> 6, kk = ml & 63;
            int m = chunk * 256 + s * 64 + kk;
            float4 kt = g_k[bhN + m];
            *(float4*)&sbuf[(kk * 4 + chunk) * 20 + 16] = kt;
        }
        __syncthreads();

        ull bq[4];
#pragma unroll
        for (int q = 0; q < 4; q++) bq[q] = mbase[q * 16 + ms * 4 + s];

        const float* row = &sbuf[ms * 20];
#pragma unroll 4
        for (int k = 0; k < 64; k++) {
            F4U w0, w1, w2r, w3, kt;
            w0.f4  = *(const float4*)(row);
            w1.f4  = *(const float4*)(row + 4);
            w2r.f4 = *(const float4*)(row + 8);
            w3.f4  = *(const float4*)(row + 12);
            kt.f4  = *(const float4*)(row + 16);
            row += 80;
#pragma unroll
            for (int q = 0; q < 4; q++) {
                float ts = si[q] + kt.f[0];
                bool pos = (ts >= 0.f);
                float w = (pos ? E1[q] : E2[q]) * (pos ? kt.f[1] : kt.f[2]);
                if (!(bq[q] & 1ULL)) w = 0.f;
                bq[q] >>= 1;
                sumw[q] += w;
                ull wp2 = pack2(w);
                fma2(acc[q][0], wp2, w0.u[0]);  fma2(acc[q][1], wp2, w0.u[1]);
                fma2(acc[q][2], wp2, w1.u[0]);  fma2(acc[q][3], wp2, w1.u[1]);
                fma2(acc[q][4], wp2, w2r.u[0]); fma2(acc[q][5], wp2, w2r.u[1]);
                fma2(acc[q][6], wp2, w3.u[0]);  fma2(acc[q][7], wp2, w3.u[1]);
            }
        }
    }

    // combine the 4 m-splits (lanes xor 1, xor 2)
#pragma unroll
    for (int q = 0; q < 4; q++) {
#pragma unroll
        for (int j = 0; j < 8; j++) {
            ull o = __shfl_xor_sync(0xffffffffu, acc[q][j], 1);
            float2 mv = *(float2*)&acc[q][j];
            float2 pv = *(float2*)&o;
            mv.x += pv.x; mv.y += pv.y; *(float2*)&acc[q][j] = mv;
            o = __shfl_xor_sync(0xffffffffu, acc[q][j], 2);
            pv = *(float2*)&o;
            mv = *(float2*)&acc[q][j];
            mv.x += pv.x; mv.y += pv.y; *(float2*)&acc[q][j] = mv;
        }
        sumw[q] += __shfl_xor_sync(0xffffffffu, sumw[q], 1);
        sumw[q] += __shfl_xor_sync(0xffffffffu, sumw[q], 2);
    }

    if (ms == 0) {
#pragma unroll
        for (int q = 0; q < 4; q++) {
            float inv = (sumw[q] > 0.f) ? __fdividef(1.f, sumw[q]) : 0.f;
            float* dst = &g_hcat[(size_t)(bN + qbase + q) * 128 + (hh << 4)];
            float2 p0 = *(float2*)&acc[q][0], p1 = *(float2*)&acc[q][1];
            float2 p2 = *(float2*)&acc[q][2], p3 = *(float2*)&acc[q][3];
            float2 p4 = *(float2*)&acc[q][4], p5 = *(float2*)&acc[q][5];
            float2 p6 = *(float2*)&acc[q][6], p7 = *(float2*)&acc[q][7];
            *(float4*)(dst)      = make_float4(p0.x*inv, p0.y*inv, p1.x*inv, p1.y*inv);
            *(float4*)(dst + 4)  = make_float4(p2.x*inv, p2.y*inv, p3.x*inv, p3.y*inv);
            *(float4*)(dst + 8)  = make_float4(p4.x*inv, p4.y*inv, p5.x*inv, p5.y*inv);
            *(float4*)(dst + 12) = make_float4(p6.x*inv, p6.y*inv, p7.x*inv, p7.y*inv);
        }
    }
}

// ---------------- LN1 (residual + layernorm) --------------------------------
__global__ __launch_bounds__(128) void ln_kernel(
        const float* __restrict__ A, const float* __restrict__ R,
        const float* __restrict__ g, const float* __restrict__ bta,
        float* __restrict__ out) {
    int row = blockIdx.x;
    int c = threadIdx.x;
    size_t basei = (size_t)row * Dd;
    float v = A[basei + c] + R[basei + c];
    float s = v, s2 = v * v;
#pragma unroll
    for (int o = 16; o > 0; o >>= 1) {
        s  += __shfl_xor_sync(0xffffffffu, s,  o);
        s2 += __shfl_xor_sync(0xffffffffu, s2, o);
    }
    __shared__ float ws[4], ws2[4];
    int w = threadIdx.x >> 5;
    if ((threadIdx.x & 31) == 0) { ws[w] = s; ws2[w] = s2; }
    __syncthreads();
    s  = ws[0]  + ws[1]  + ws[2]  + ws[3];
    s2 = ws2[0] + ws2[1] + ws2[2] + ws2[3];
    float mu  = s * (1.f / Dd);
    float var = s2 * (1.f / Dd) - mu * mu;
    float r = rsqrtf(var + EPSc);
    out[basei + c] = (v - mu) * r * g[c] + bta[c];
}

// ---------------- launch ----------------------------------------------------
extern "C" void kernel_launch(void* const* d_in, const int* in_sizes, int n_in,
                              void* d_out, int out_size) {
    const float* h    = (const float*)d_in[0];
    const int*   adj  = (const int*)d_in[1];
    const float* W    = (const float*)d_in[2];
    const float* a    = (const float*)d_in[3];
    const float* ln1g = (const float*)d_in[4];
    const float* ln1b = (const float*)d_in[5];
    const float* w1   = (const float*)d_in[6];
    const float* b1   = (const float*)d_in[7];
    const float* w2   = (const float*)d_in[8];
    const float* b2   = (const float*)d_in[9];
    const float* ln2g = (const float*)d_in[10];
    const float* ln2b = (const float*)d_in[11];
    float* out = (float*)d_out;

    float *Wt, *Wh, *hcat, *x, *y;
    cudaGetSymbolAddress((void**)&Wt,   g_Wt);
    cudaGetSymbolAddress((void**)&Wh,   g_Wh);
    cudaGetSymbolAddress((void**)&hcat, g_hcat);
    cudaGetSymbolAddress((void**)&x,    g_x);
    cudaGetSymbolAddress((void**)&y,    g_y);

    pack_mask_kernel<<<(Bb * Nn * Nn) / 1024, 256>>>((const int4*)adj);
    transpose_w_kernel<<<(Dd * Dd) / 1024, 1024>>>(W);
    // Wh + score/exp tables (fused)
    gemm_kernel<0><<<dim3(1, ROWS / 64), 256>>>(h, Wt, nullptr, a, nullptr, nullptr,
                                                Wh, Dd, Dd);
    // attention
    att_kernel<<<dim3(Nn / 128, Hh, Bb), 128>>>();
    // LN1(hcat + h) -> x
    ln_kernel<<<ROWS, Dd>>>(hcat, h, ln1g, ln1b, x);
    // y = relu(x @ w1 + b1)
    gemm_kernel<1><<<dim3(2, ROWS / 64), 256>>>(x, w1, b1, nullptr, nullptr, nullptr,
                                                y, Dd, 2 * Dd);
    // out = LN2(x + y @ w2 + b2)
    gemm_kernel<2><<<dim3(1, ROWS / 64), 256>>>(y, w2, b2, x, ln2g, ln2b,
                                                out, 2 * Dd, Dd);
}

// round 7
// speedup vs baseline: 1.5747x; 1.0500x over previous
#include <cuda_runtime.h>
#include <cuda_bf16.h>
#include <cstdint>

#define Bb   8
#define Nn   1024
#define Hh   8
#define Dd   128
#define ROWS (Bb*Nn)      // 8192
#define EPSc 1e-5f

typedef unsigned long long ull;

// ---------------- scratch (static; no cudaMalloc) ---------------------------
__device__ float  g_Wt[Dd*Dd];
__device__ float  g_Wh[ROWS*Dd];
__device__ float4 g_q[Bb*Hh*Nn];   // {s_i, e^{s_i}, e^{0.2 s_i}, 0}
__device__ float4 g_k[Bb*Hh*Nn];
__device__ ull    g_maskbits[(size_t)ROWS*Nn/64];
__device__ float  g_hcat[ROWS*Dd];
__device__ float  g_x[ROWS*Dd];
__device__ float  g_y[ROWS*2*Dd];

// ---------------- helpers ---------------------------------------------------
__device__ __forceinline__ ull pack2(float x) {
    ull r;
    asm("mov.b64 %0, {%1, %1};" : "=l"(r) : "f"(x));
    return r;
}
__device__ __forceinline__ void fma2(ull& acc, ull ab, ull c) {
    asm("fma.rn.f32x2 %0, %1, %2, %0;" : "+l"(acc) : "l"(ab), "l"(c));
}
union F4U { float4 f4; ull u[2]; float f[4]; };

// ---------------- 1. pack mask bits + reorder W (fused) ---------------------
__global__ __launch_bounds__(256) void prep_kernel(const int4* __restrict__ adj4,
                                                   const float* __restrict__ W) {
    __shared__ unsigned char nib[256];
    int t = threadIdx.x;
    int4 v = adj4[(size_t)blockIdx.x * 256 + t];
    unsigned n = (v.x != 0) | ((v.y != 0) << 1) | ((v.z != 0) << 2) | ((v.w != 0) << 3);
    nib[t] = (unsigned char)n;
    // blocks 0..63 additionally reorder W (H,IN,HD) -> Wt (IN, H*HD)
    if (blockIdx.x < 64) {
        int tid = blockIdx.x * 256 + t;      // < 16384
        int i = tid >> 7;
        int o = tid & 127;
        int hh = o >> 4, d = o & 15;
        g_Wt[tid] = W[(hh << 11) + (i << 4) + d];
    }
    __syncthreads();
    if (t < 16) {
        uint4 bytes = *(const uint4*)(nib + t * 16);
        unsigned w[4] = {bytes.x, bytes.y, bytes.z, bytes.w};
        ull word = 0;
#pragma unroll
        for (int i = 0; i < 4; i++) {
            unsigned x = w[i];
            unsigned o = (x & 0xFu) | ((x >> 4) & 0xF0u) |
                         ((x >> 8) & 0xF00u) | ((x >> 12) & 0xF000u);
            word |= (ull)o << (16 * i);
        }
        g_maskbits[(size_t)blockIdx.x * 16 + t] = word;
    }
}

// ---------------- fused 64x128-tile SGEMM (f32x2 core), 3 modes -------------
// MODE 0: C=Wh = A@B, epilogue -> score exp tables g_q/g_k
// MODE 1: C = relu(A@B + bias)
// MODE 2: C = LayerNorm(extra + A@B + bias)*gam+bet
template<int MODE>
__global__ __launch_bounds__(256) void gemm_kernel(
        const float* __restrict__ A, const float* __restrict__ Bm,
        const float* __restrict__ bias, const float* __restrict__ extra,
        const float* __restrict__ gam, const float* __restrict__ bet,
        float* __restrict__ C, int K, int N) {
    __shared__ float As[16][68];
    __shared__ float Bs[16][128];
    __shared__ float sa_src[128], sa_dst[128];
    int t  = threadIdx.x;
    int tx = t & 15, ty = t >> 4;
    int row0 = blockIdx.y * 64;
    int col0 = blockIdx.x * 128;

    if (MODE == 0 && t < 128) {
        int hh = t >> 4, d = t & 15;
        sa_src[t] = extra[hh * 32 + d];
        sa_dst[t] = extra[hh * 32 + 16 + d];
    }

    ull acc2[4][4];
#pragma unroll
    for (int i = 0; i < 4; i++)
#pragma unroll
        for (int j = 0; j < 4; j++) acc2[i][j] = 0ULL;

    int arow = t >> 2, ak = (t & 3) << 2;
    for (int k0 = 0; k0 < K; k0 += 16) {
        float4 av = *(const float4*)&A[(size_t)(row0 + arow) * K + k0 + ak];
        int brow0 = t >> 5, bcol = (t & 31) << 2;
        float4 b0 = *(const float4*)&Bm[(size_t)(k0 + brow0) * N + col0 + bcol];
        float4 b1 = *(const float4*)&Bm[(size_t)(k0 + brow0 + 8) * N + col0 + bcol];
        __syncthreads();
        As[ak + 0][arow] = av.x; As[ak + 1][arow] = av.y;
        As[ak + 2][arow] = av.z; As[ak + 3][arow] = av.w;
        *(float4*)&Bs[brow0][bcol]     = b0;
        *(float4*)&Bs[brow0 + 8][bcol] = b1;
        __syncthreads();
#pragma unroll
        for (int k = 0; k < 16; k++) {
            float4 a4 = *(const float4*)&As[k][ty << 2];
            F4U q0, q1;
            q0.f4 = *(const float4*)&Bs[k][tx << 3];
            q1.f4 = *(const float4*)&Bs[k][(tx << 3) + 4];
            ull bp[4] = {q0.u[0], q0.u[1], q1.u[0], q1.u[1]};
            ull ap[4] = {pack2(a4.x), pack2(a4.y), pack2(a4.z), pack2(a4.w)};
#pragma unroll
            for (int i = 0; i < 4; i++)
#pragma unroll
                for (int j = 0; j < 4; j++) fma2(acc2[i][j], ap[i], bp[j]);
        }
    }

    float acc[4][8];
#pragma unroll
    for (int i = 0; i < 4; i++)
#pragma unroll
        for (int j = 0; j < 4; j++) {
            float2 p = *(float2*)&acc2[i][j];
            acc[i][2 * j]     = p.x;
            acc[i][2 * j + 1] = p.y;
        }

    if (MODE == 0) {
#pragma unroll
        for (int i = 0; i < 4; i++) {
            int r = row0 + (ty << 2) + i;
            *(float4*)&C[(size_t)r * 128 + (tx << 3)] =
                make_float4(acc[i][0], acc[i][1], acc[i][2], acc[i][3]);
            *(float4*)&C[(size_t)r * 128 + (tx << 3) + 4] =
                make_float4(acc[i][4], acc[i][5], acc[i][6], acc[i][7]);
            float sp = 0.f, dp = 0.f;
#pragma unroll
            for (int j = 0; j < 8; j++) {
                sp += acc[i][j] * sa_src[(tx << 3) + j];
                dp += acc[i][j] * sa_dst[(tx << 3) + j];
            }
            sp += __shfl_xor_sync(0xffffffffu, sp, 1);
            dp += __shfl_xor_sync(0xffffffffu, dp, 1);
            if (!(tx & 1)) {
                int b = r >> 10, n = r & 1023;
                int hh = tx >> 1;
                int idx = ((b << 3) + hh) * 1024 + n;
                g_q[idx] = make_float4(sp, __expf(sp), __expf(0.2f * sp), 0.f);
                g_k[idx] = make_float4(dp, __expf(dp), __expf(0.2f * dp), 0.f);
            }
        }
    } else if (MODE == 1) {
        float bv[8];
#pragma unroll
        for (int j = 0; j < 8; j++) bv[j] = bias[col0 + (tx << 3) + j];
#pragma unroll
        for (int i = 0; i < 4; i++) {
            int r = row0 + (ty << 2) + i;
            float4 r0, r1;
            r0.x = fmaxf(acc[i][0] + bv[0], 0.f); r0.y = fmaxf(acc[i][1] + bv[1], 0.f);
            r0.z = fmaxf(acc[i][2] + bv[2], 0.f); r0.w = fmaxf(acc[i][3] + bv[3], 0.f);
            r1.x = fmaxf(acc[i][4] + bv[4], 0.f); r1.y = fmaxf(acc[i][5] + bv[5], 0.f);
            r1.z = fmaxf(acc[i][6] + bv[6], 0.f); r1.w = fmaxf(acc[i][7] + bv[7], 0.f);
            *(float4*)&C[(size_t)r * N + col0 + (tx << 3)]     = r0;
            *(float4*)&C[(size_t)r * N + col0 + (tx << 3) + 4] = r1;
        }
    } else {
        float bv[8], gv[8], bb[8];
#pragma unroll
        for (int j = 0; j < 8; j++) {
            bv[j] = bias[(tx << 3) + j];
            gv[j] = gam[(tx << 3) + j];
            bb[j] = bet[(tx << 3) + j];
        }
#pragma unroll
        for (int i = 0; i < 4; i++) {
            int r = row0 + (ty << 2) + i;
            float4 x0 = *(const float4*)&extra[(size_t)r * 128 + (tx << 3)];
            float4 x1 = *(const float4*)&extra[(size_t)r * 128 + (tx << 3) + 4];
            float v[8] = {x0.x, x0.y, x0.z, x0.w, x1.x, x1.y, x1.z, x1.w};
            float s = 0.f, s2 = 0.f;
#pragma unroll
            for (int j = 0; j < 8; j++) {
                v[j] += acc[i][j] + bv[j];
                s += v[j]; s2 += v[j] * v[j];
            }
#pragma unroll
            for (int o = 1; o <= 8; o <<= 1) {
                s  += __shfl_xor_sync(0xffffffffu, s,  o);
                s2 += __shfl_xor_sync(0xffffffffu, s2, o);
            }
            float mu  = s * (1.f / 128.f);
            float var = s2 * (1.f / 128.f) - mu * mu;
            float rs  = rsqrtf(var + EPSc);
            float4 r0, r1;
            r0.x = (v[0]-mu)*rs*gv[0]+bb[0]; r0.y = (v[1]-mu)*rs*gv[1]+bb[1];
            r0.z = (v[2]-mu)*rs*gv[2]+bb[2]; r0.w = (v[3]-mu)*rs*gv[3]+bb[3];
            r1.x = (v[4]-mu)*rs*gv[4]+bb[4]; r1.y = (v[5]-mu)*rs*gv[5]+bb[5];
            r1.z = (v[6]-mu)*rs*gv[6]+bb[6]; r1.w = (v[7]-mu)*rs*gv[7]+bb[7];
            *(float4*)&C[(size_t)r * 128 + (tx << 3)]     = r0;
            *(float4*)&C[(size_t)r * 128 + (tx << 3) + 4] = r1;
        }
    }
}

// ---------------- fused masked-softmax attention (max-trick) ----------------
// grid (16, H, B), block 128. Lane l: ms = l&3 (m-split), qg = wp*8 + (l>>2).
// Thread: 2 queries (qbase, qbase+1), m in [ms*256, ms*256+256).
// Key identity: weight = max(e^{si}*e^{sj}, e^{0.2si}*e^{0.2sj}).
// Staged smem row (80B): [16 Wh floats][e^sj, e^0.2sj][pad x2].
__global__ __launch_bounds__(128, 6) void att_kernel() {
    __shared__ float sbuf[256 * 20];   // 20 KB
    int b = blockIdx.z, hh = blockIdx.y;
    int t = threadIdx.x;
    int l = t & 31, wp = t >> 5;
    int ms = l & 3;
    int qbase = blockIdx.x * 64 + (wp * 8 + (l >> 2)) * 2;
    int bN = b * Nn, bhN = (b * Hh + hh) * Nn;

    float E1[2], E2[2];
#pragma unroll
    for (int q = 0; q < 2; q++) {
        float4 qq = g_q[bhN + qbase + q];
        E1[q] = qq.y; E2[q] = qq.z;
    }
    const ull* mbase = g_maskbits + (size_t)(bN + qbase) * 16;

    ull acc[2][8];
#pragma unroll
    for (int q = 0; q < 2; q++)
#pragma unroll
        for (int j = 0; j < 8; j++) acc[q][j] = 0ULL;
    float sumw[2] = {0.f, 0.f};

    for (int s = 0; s < 4; s++) {
        __syncthreads();
        // stage Wh: row r = kk*4 + chunk <- m = chunk*256 + s*64 + kk
#pragma unroll
        for (int u = 0; u < 8; u++) {
            int fi = u * 128 + t;            // (m-local, j)
            int ml = fi >> 2, j = fi & 3;
            int chunk = ml >> 6, kk = ml & 63;
            int m = chunk * 256 + s * 64 + kk;
            float4 v = *(const float4*)&g_Wh[(size_t)(bN + m) * 128 + (hh << 4) + (j << 2)];
            *(float4*)&sbuf[(kk * 4 + chunk) * 20 + (j << 2)] = v;
        }
#pragma unroll
        for (int u = 0; u < 2; u++) {
            int ml = u * 128 + t;
            int chunk = ml >> 6, kk = ml & 63;
            int m = chunk * 256 + s * 64 + kk;
            float4 kt = g_k[bhN + m];
            *(float2*)&sbuf[(kk * 4 + chunk) * 20 + 16] = make_float2(kt.y, kt.z);
        }
        __syncthreads();

        ull bq0 = mbase[ms * 4 + s];
        ull bq1 = mbase[16 + ms * 4 + s];

        const float* row = &sbuf[ms * 20];
#pragma unroll 4
        for (int k = 0; k < 64; k++) {
            F4U w0, w1, w2r, w3;
            w0.f4  = *(const float4*)(row);
            w1.f4  = *(const float4*)(row + 4);
            w2r.f4 = *(const float4*)(row + 8);
            w3.f4  = *(const float4*)(row + 12);
            float2 kp = *(const float2*)(row + 16);
            row += 80;

            float wa = fmaxf(E1[0] * kp.x, E2[0] * kp.y);
            if (!(bq0 & 1ULL)) wa = 0.f;
            bq0 >>= 1;
            sumw[0] += wa;
            ull wpa = pack2(wa);
            fma2(acc[0][0], wpa, w0.u[0]);  fma2(acc[0][1], wpa, w0.u[1]);
            fma2(acc[0][2], wpa, w1.u[0]);  fma2(acc[0][3], wpa, w1.u[1]);
            fma2(acc[0][4], wpa, w2r.u[0]); fma2(acc[0][5], wpa, w2r.u[1]);
            fma2(acc[0][6], wpa, w3.u[0]);  fma2(acc[0][7], wpa, w3.u[1]);

            float wb = fmaxf(E1[1] * kp.x, E2[1] * kp.y);
            if (!(bq1 & 1ULL)) wb = 0.f;
            bq1 >>= 1;
            sumw[1] += wb;
            ull wpb = pack2(wb);
            fma2(acc[1][0], wpb, w0.u[0]);  fma2(acc[1][1], wpb, w0.u[1]);
            fma2(acc[1][2], wpb, w1.u[0]);  fma2(acc[1][3], wpb, w1.u[1]);
            fma2(acc[1][4], wpb, w2r.u[0]); fma2(acc[1][5], wpb, w2r.u[1]);
            fma2(acc[1][6], wpb, w3.u[0]);  fma2(acc[1][7], wpb, w3.u[1]);
        }
    }

    // combine the 4 m-splits (lanes xor 1, xor 2 share the same q-pair)
#pragma unroll
    for (int q = 0; q < 2; q++) {
#pragma unroll
        for (int j = 0; j < 8; j++) {
            ull o = __shfl_xor_sync(0xffffffffu, acc[q][j], 1);
            float2 mv = *(float2*)&acc[q][j];
            float2 pv = *(float2*)&o;
            mv.x += pv.x; mv.y += pv.y; *(float2*)&acc[q][j] = mv;
            o = __shfl_xor_sync(0xffffffffu, acc[q][j], 2);
            pv = *(float2*)&o;
            mv = *(float2*)&acc[q][j];
            mv.x += pv.x; mv.y += pv.y; *(float2*)&acc[q][j] = mv;
        }
        sumw[q] += __shfl_xor_sync(0xffffffffu, sumw[q], 1);
        sumw[q] += __shfl_xor_sync(0xffffffffu, sumw[q], 2);
    }

    if (ms == 0) {
#pragma unroll
        for (int q = 0; q < 2; q++) {
            float inv = (sumw[q] > 0.f) ? __fdividef(1.f, sumw[q]) : 0.f;
            float* dst = &g_hcat[(size_t)(bN + qbase + q) * 128 + (hh << 4)];
            float2 p0 = *(float2*)&acc[q][0], p1 = *(float2*)&acc[q][1];
            float2 p2 = *(float2*)&acc[q][2], p3 = *(float2*)&acc[q][3];
            float2 p4 = *(float2*)&acc[q][4], p5 = *(float2*)&acc[q][5];
            float2 p6 = *(float2*)&acc[q][6], p7 = *(float2*)&acc[q][7];
            *(float4*)(dst)      = make_float4(p0.x*inv, p0.y*inv, p1.x*inv, p1.y*inv);
            *(float4*)(dst + 4)  = make_float4(p2.x*inv, p2.y*inv, p3.x*inv, p3.y*inv);
            *(float4*)(dst + 8)  = make_float4(p4.x*inv, p4.y*inv, p5.x*inv, p5.y*inv);
            *(float4*)(dst + 12) = make_float4(p6.x*inv, p6.y*inv, p7.x*inv, p7.y*inv);
        }
    }
}

// ---------------- LN1: warp-per-row, float4, shuffle-only reduce ------------
__global__ __launch_bounds__(256) void ln_kernel(
        const float* __restrict__ A, const float* __restrict__ R,
        const float* __restrict__ g, const float* __restrict__ bta,
        float* __restrict__ out) {
    int wp = threadIdx.x >> 5, l = threadIdx.x & 31;
    int row = blockIdx.x * 8 + wp;
    size_t base = (size_t)row * Dd + (l << 2);
    float4 a4 = *(const float4*)&A[base];
    float4 r4 = *(const float4*)&R[base];
    float v[4] = {a4.x + r4.x, a4.y + r4.y, a4.z + r4.z, a4.w + r4.w};
    float s = v[0] + v[1] + v[2] + v[3];
    float s2 = v[0]*v[0] + v[1]*v[1] + v[2]*v[2] + v[3]*v[3];
#pragma unroll
    for (int o = 16; o > 0; o >>= 1) {
        s  += __shfl_xor_sync(0xffffffffu, s,  o);
        s2 += __shfl_xor_sync(0xffffffffu, s2, o);
    }
    float mu  = s * (1.f / Dd);
    float var = s2 * (1.f / Dd) - mu * mu;
    float rs = rsqrtf(var + EPSc);
    float4 g4 = *(const float4*)&g[l << 2];
    float4 b4 = *(const float4*)&bta[l << 2];
    float4 o4;
    o4.x = (v[0]-mu)*rs*g4.x + b4.x; o4.y = (v[1]-mu)*rs*g4.y + b4.y;
    o4.z = (v[2]-mu)*rs*g4.z + b4.z; o4.w = (v[3]-mu)*rs*g4.w + b4.w;
    *(float4*)&out[base] = o4;
}

// ---------------- launch ----------------------------------------------------
extern "C" void kernel_launch(void* const* d_in, const int* in_sizes, int n_in,
                              void* d_out, int out_size) {
    const float* h    = (const float*)d_in[0];
    const int*   adj  = (const int*)d_in[1];
    const float* W    = (const float*)d_in[2];
    const float* a    = (const float*)d_in[3];
    const float* ln1g = (const float*)d_in[4];
    const float* ln1b = (const float*)d_in[5];
    const float* w1   = (const float*)d_in[6];
    const float* b1   = (const float*)d_in[7];
    const float* w2   = (const float*)d_in[8];
    const float* b2   = (const float*)d_in[9];
    const float* ln2g = (const float*)d_in[10];
    const float* ln2b = (const float*)d_in[11];
    float* out = (float*)d_out;

    float *Wt, *Wh, *hcat, *x, *y;
    cudaGetSymbolAddress((void**)&Wt,   g_Wt);
    cudaGetSymbolAddress((void**)&Wh,   g_Wh);
    cudaGetSymbolAddress((void**)&hcat, g_hcat);
    cudaGetSymbolAddress((void**)&x,    g_x);
    cudaGetSymbolAddress((void**)&y,    g_y);

    // mask pack + W reorder (fused)
    prep_kernel<<<(Bb * Nn * Nn) / 1024, 256>>>((const int4*)adj, W);
    // Wh + score/exp tables (fused)
    gemm_kernel<0><<<dim3(1, ROWS / 64), 256>>>(h, Wt, nullptr, a, nullptr, nullptr,
                                                Wh, Dd, Dd);
    // attention
    att_kernel<<<dim3(Nn / 64, Hh, Bb), 128>>>();
    // LN1(hcat + h) -> x
    ln_kernel<<<ROWS / 8, 256>>>(hcat, h, ln1g, ln1b, x);
    // y = relu(x @ w1 + b1)
    gemm_kernel<1><<<dim3(2, ROWS / 64), 256>>>(x, w1, b1, nullptr, nullptr, nullptr,
                                                y, Dd, 2 * Dd);
    // out = LN2(x + y @ w2 + b2)
    gemm_kernel<2><<<dim3(1, ROWS / 64), 256>>>(y, w2, b2, x, ln2g, ln2b,
                                                out, 2 * Dd, Dd);
}

// round 8
// speedup vs baseline: 1.7661x; 1.1215x over previous
#include <cuda_runtime.h>
#include <cuda_bf16.h>
#include <cstdint>

#define Bb   8
#define Nn   1024
#define Hh   8
#define Dd   128
#define ROWS (Bb*Nn)      // 8192
#define EPSc 1e-5f

typedef unsigned long long ull;

// ---------------- scratch (static; no cudaMalloc) ---------------------------
__device__ float  g_Wt[Dd*Dd];
__device__ float  g_Wh[ROWS*Dd];
__device__ float4 g_q[Bb*Hh*Nn];   // {s_i, e^{s_i}, e^{0.2 s_i}, 0}
__device__ float4 g_k[Bb*Hh*Nn];
__device__ ull    g_maskbits[(size_t)ROWS*Nn/64];
__device__ float  g_hcat[ROWS*Dd];
__device__ float  g_x[ROWS*Dd];
__device__ float  g_y[ROWS*2*Dd];

// ---------------- helpers ---------------------------------------------------
__device__ __forceinline__ ull pack2(float x) {
    ull r;
    asm("mov.b64 %0, {%1, %1};" : "=l"(r) : "f"(x));
    return r;
}
__device__ __forceinline__ void fma2(ull& acc, ull ab, ull c) {
    asm("fma.rn.f32x2 %0, %1, %2, %0;" : "+l"(acc) : "l"(ab), "l"(c));
}
union F4U { float4 f4; ull u[2]; float f[4]; };

// ---------------- 1. pack mask bits + reorder W (fused) ---------------------
__global__ __launch_bounds__(256) void prep_kernel(const int4* __restrict__ adj4,
                                                   const float* __restrict__ W) {
    __shared__ unsigned char nib[256];
    int t = threadIdx.x;
    int4 v = adj4[(size_t)blockIdx.x * 256 + t];
    unsigned n = (v.x != 0) | ((v.y != 0) << 1) | ((v.z != 0) << 2) | ((v.w != 0) << 3);
    nib[t] = (unsigned char)n;
    if (blockIdx.x < 64) {
        int tid = blockIdx.x * 256 + t;      // < 16384
        int i = tid >> 7;
        int o = tid & 127;
        int hh = o >> 4, d = o & 15;
        g_Wt[tid] = W[(hh << 11) + (i << 4) + d];
    }
    __syncthreads();
    if (t < 16) {
        uint4 bytes = *(const uint4*)(nib + t * 16);
        unsigned w[4] = {bytes.x, bytes.y, bytes.z, bytes.w};
        ull word = 0;
#pragma unroll
        for (int i = 0; i < 4; i++) {
            unsigned x = w[i];
            unsigned o = (x & 0xFu) | ((x >> 4) & 0xF0u) |
                         ((x >> 8) & 0xF00u) | ((x >> 12) & 0xF000u);
            word |= (ull)o << (16 * i);
        }
        g_maskbits[(size_t)blockIdx.x * 16 + t] = word;
    }
}

// ---------------- fused 64x128-tile SGEMM (f32x2 core), 3 modes -------------
template<int MODE>
__global__ __launch_bounds__(256) void gemm_kernel(
        const float* __restrict__ A, const float* __restrict__ Bm,
        const float* __restrict__ bias, const float* __restrict__ extra,
        const float* __restrict__ gam, const float* __restrict__ bet,
        float* __restrict__ C, int K, int N) {
    __shared__ float As[16][68];
    __shared__ float Bs[16][128];
    __shared__ float sa_src[128], sa_dst[128];
    int t  = threadIdx.x;
    int tx = t & 15, ty = t >> 4;
    int row0 = blockIdx.y * 64;
    int col0 = blockIdx.x * 128;

    if (MODE == 0 && t < 128) {
        int hh = t >> 4, d = t & 15;
        sa_src[t] = extra[hh * 32 + d];
        sa_dst[t] = extra[hh * 32 + 16 + d];
    }

    ull acc2[4][4];
#pragma unroll
    for (int i = 0; i < 4; i++)
#pragma unroll
        for (int j = 0; j < 4; j++) acc2[i][j] = 0ULL;

    int arow = t >> 2, ak = (t & 3) << 2;
    for (int k0 = 0; k0 < K; k0 += 16) {
        float4 av = *(const float4*)&A[(size_t)(row0 + arow) * K + k0 + ak];
        int brow0 = t >> 5, bcol = (t & 31) << 2;
        float4 b0 = *(const float4*)&Bm[(size_t)(k0 + brow0) * N + col0 + bcol];
        float4 b1 = *(const float4*)&Bm[(size_t)(k0 + brow0 + 8) * N + col0 + bcol];
        __syncthreads();
        As[ak + 0][arow] = av.x; As[ak + 1][arow] = av.y;
        As[ak + 2][arow] = av.z; As[ak + 3][arow] = av.w;
        *(float4*)&Bs[brow0][bcol]     = b0;
        *(float4*)&Bs[brow0 + 8][bcol] = b1;
        __syncthreads();
#pragma unroll
        for (int k = 0; k < 16; k++) {
            float4 a4 = *(const float4*)&As[k][ty << 2];
            F4U q0, q1;
            q0.f4 = *(const float4*)&Bs[k][tx << 3];
            q1.f4 = *(const float4*)&Bs[k][(tx << 3) + 4];
            ull bp[4] = {q0.u[0], q0.u[1], q1.u[0], q1.u[1]};
            ull ap[4] = {pack2(a4.x), pack2(a4.y), pack2(a4.z), pack2(a4.w)};
#pragma unroll
            for (int i = 0; i < 4; i++)
#pragma unroll
                for (int j = 0; j < 4; j++) fma2(acc2[i][j], ap[i], bp[j]);
        }
    }

    float acc[4][8];
#pragma unroll
    for (int i = 0; i < 4; i++)
#pragma unroll
        for (int j = 0; j < 4; j++) {
            float2 p = *(float2*)&acc2[i][j];
            acc[i][2 * j]     = p.x;
            acc[i][2 * j + 1] = p.y;
        }

    if (MODE == 0) {
#pragma unroll
        for (int i = 0; i < 4; i++) {
            int r = row0 + (ty << 2) + i;
            *(float4*)&C[(size_t)r * 128 + (tx << 3)] =
                make_float4(acc[i][0], acc[i][1], acc[i][2], acc[i][3]);
            *(float4*)&C[(size_t)r * 128 + (tx << 3) + 4] =
                make_float4(acc[i][4], acc[i][5], acc[i][6], acc[i][7]);
            float sp = 0.f, dp = 0.f;
#pragma unroll
            for (int j = 0; j < 8; j++) {
                sp += acc[i][j] * sa_src[(tx << 3) + j];
                dp += acc[i][j] * sa_dst[(tx << 3) + j];
            }
            sp += __shfl_xor_sync(0xffffffffu, sp, 1);
            dp += __shfl_xor_sync(0xffffffffu, dp, 1);
            if (!(tx & 1)) {
                int b = r >> 10, n = r & 1023;
                int hh = tx >> 1;
                int idx = ((b << 3) + hh) * 1024 + n;
                g_q[idx] = make_float4(sp, __expf(sp), __expf(0.2f * sp), 0.f);
                g_k[idx] = make_float4(dp, __expf(dp), __expf(0.2f * dp), 0.f);
            }
        }
    } else if (MODE == 1) {
        float bv[8];
#pragma unroll
        for (int j = 0; j < 8; j++) bv[j] = bias[col0 + (tx << 3) + j];
#pragma unroll
        for (int i = 0; i < 4; i++) {
            int r = row0 + (ty << 2) + i;
            float4 r0, r1;
            r0.x = fmaxf(acc[i][0] + bv[0], 0.f); r0.y = fmaxf(acc[i][1] + bv[1], 0.f);
            r0.z = fmaxf(acc[i][2] + bv[2], 0.f); r0.w = fmaxf(acc[i][3] + bv[3], 0.f);
            r1.x = fmaxf(acc[i][4] + bv[4], 0.f); r1.y = fmaxf(acc[i][5] + bv[5], 0.f);
            r1.z = fmaxf(acc[i][6] + bv[6], 0.f); r1.w = fmaxf(acc[i][7] + bv[7], 0.f);
            *(float4*)&C[(size_t)r * N + col0 + (tx << 3)]     = r0;
            *(float4*)&C[(size_t)r * N + col0 + (tx << 3) + 4] = r1;
        }
    } else {
        float bv[8], gv[8], bb[8];
#pragma unroll
        for (int j = 0; j < 8; j++) {
            bv[j] = bias[(tx << 3) + j];
            gv[j] = gam[(tx << 3) + j];
            bb[j] = bet[(tx << 3) + j];
        }
#pragma unroll
        for (int i = 0; i < 4; i++) {
            int r = row0 + (ty << 2) + i;
            float4 x0 = *(const float4*)&extra[(size_t)r * 128 + (tx << 3)];
            float4 x1 = *(const float4*)&extra[(size_t)r * 128 + (tx << 3) + 4];
            float v[8] = {x0.x, x0.y, x0.z, x0.w, x1.x, x1.y, x1.z, x1.w};
            float s = 0.f, s2 = 0.f;
#pragma unroll
            for (int j = 0; j < 8; j++) {
                v[j] += acc[i][j] + bv[j];
                s += v[j]; s2 += v[j] * v[j];
            }
#pragma unroll
            for (int o = 1; o <= 8; o <<= 1) {
                s  += __shfl_xor_sync(0xffffffffu, s,  o);
                s2 += __shfl_xor_sync(0xffffffffu, s2, o);
            }
            float mu  = s * (1.f / 128.f);
            float var = s2 * (1.f / 128.f) - mu * mu;
            float rs  = rsqrtf(var + EPSc);
            float4 r0, r1;
            r0.x = (v[0]-mu)*rs*gv[0]+bb[0]; r0.y = (v[1]-mu)*rs*gv[1]+bb[1];
            r0.z = (v[2]-mu)*rs*gv[2]+bb[2]; r0.w = (v[3]-mu)*rs*gv[3]+bb[3];
            r1.x = (v[4]-mu)*rs*gv[4]+bb[4]; r1.y = (v[5]-mu)*rs*gv[5]+bb[5];
            r1.z = (v[6]-mu)*rs*gv[6]+bb[6]; r1.w = (v[7]-mu)*rs*gv[7]+bb[7];
            *(float4*)&C[(size_t)r * 128 + (tx << 3)]     = r0;
            *(float4*)&C[(size_t)r * 128 + (tx << 3) + 4] = r1;
        }
    }
}

// ---------------- fused masked-softmax attention ----------------------------
// grid (8, H, B), block 128. Lane l: ms = l&3 (m-split), qg = wp*8 + (l>>2).
// Thread: 4 queries, m in [ms*256, ms*256+256) staged in 4 chunks of 64.
// weight = max(e^{si}*e^{sj}, e^{0.2si}*e^{0.2sj}) (monotone-exp identity).
// Staged smem row (80B): [16 Wh floats][e^sj, e^0.2sj][pad x2].
__global__ __launch_bounds__(128, 4) void att_kernel() {
    __shared__ float sbuf[256 * 20];   // 20 KB
    int b = blockIdx.z, hh = blockIdx.y;
    int t = threadIdx.x;
    int l = t & 31, wp = t >> 5;
    int ms = l & 3;
    int qbase = blockIdx.x * 128 + (wp * 8 + (l >> 2)) * 4;
    int bN = b * Nn, bhN = (b * Hh + hh) * Nn;

    float E1[4], E2[4];
#pragma unroll
    for (int q = 0; q < 4; q++) {
        float4 qq = g_q[bhN + qbase + q];
        E1[q] = qq.y; E2[q] = qq.z;
    }
    const ull* mbase = g_maskbits + (size_t)(bN + qbase) * 16;

    ull acc[4][8];
#pragma unroll
    for (int q = 0; q < 4; q++)
#pragma unroll
        for (int j = 0; j < 8; j++) acc[q][j] = 0ULL;
    float sumw[4] = {0.f, 0.f, 0.f, 0.f};

    for (int s = 0; s < 4; s++) {
        __syncthreads();
        // stage Wh: row r = kk*4 + chunk <- m = chunk*256 + s*64 + kk
#pragma unroll
        for (int u = 0; u < 8; u++) {
            int fi = u * 128 + t;            // (m-local, j)
            int ml = fi >> 2, j = fi & 3;
            int chunk = ml >> 6, kk = ml & 63;
            int m = chunk * 256 + s * 64 + kk;
            float4 v = *(const float4*)&g_Wh[(size_t)(bN + m) * 128 + (hh << 4) + (j << 2)];
            *(float4*)&sbuf[(kk * 4 + chunk) * 20 + (j << 2)] = v;
        }
#pragma unroll
        for (int u = 0; u < 2; u++) {
            int ml = u * 128 + t;
            int chunk = ml >> 6, kk = ml & 63;
            int m = chunk * 256 + s * 64 + kk;
            float4 kt = g_k[bhN + m];
            *(float2*)&sbuf[(kk * 4 + chunk) * 20 + 16] = make_float2(kt.y, kt.z);
        }
        __syncthreads();

        ull bq[4];
#pragma unroll
        for (int q = 0; q < 4; q++) bq[q] = mbase[q * 16 + ms * 4 + s];

        const float* row = &sbuf[ms * 20];
        for (int k8 = 0; k8 < 8; k8++) {
#pragma unroll
            for (int j = 0; j < 8; j++) {
                F4U w0, w1, w2r, w3;
                w0.f4  = *(const float4*)(row + j * 80);
                w1.f4  = *(const float4*)(row + j * 80 + 4);
                w2r.f4 = *(const float4*)(row + j * 80 + 8);
                w3.f4  = *(const float4*)(row + j * 80 + 12);
                float2 kp = *(const float2*)(row + j * 80 + 16);
#pragma unroll
                for (int q = 0; q < 4; q++) {
                    float w = fmaxf(E1[q] * kp.x, E2[q] * kp.y);
                    w = ((unsigned)bq[q] & (1u << j)) ? w : 0.f;
                    sumw[q] += w;
                    ull wp2 = pack2(w);
                    fma2(acc[q][0], wp2, w0.u[0]);  fma2(acc[q][1], wp2, w0.u[1]);
                    fma2(acc[q][2], wp2, w1.u[0]);  fma2(acc[q][3], wp2, w1.u[1]);
                    fma2(acc[q][4], wp2, w2r.u[0]); fma2(acc[q][5], wp2, w2r.u[1]);
                    fma2(acc[q][6], wp2, w3.u[0]);  fma2(acc[q][7], wp2, w3.u[1]);
                }
            }
#pragma unroll
            for (int q = 0; q < 4; q++) bq[q] >>= 8;
            row += 640;
        }
    }

    // combine the 4 m-splits (lanes xor 1, xor 2 share the same q-quad)
#pragma unroll
    for (int q = 0; q < 4; q++) {
#pragma unroll
        for (int j = 0; j < 8; j++) {
            ull o = __shfl_xor_sync(0xffffffffu, acc[q][j], 1);
            float2 mv = *(float2*)&acc[q][j];
            float2 pv = *(float2*)&o;
            mv.x += pv.x; mv.y += pv.y; *(float2*)&acc[q][j] = mv;
            o = __shfl_xor_sync(0xffffffffu, acc[q][j], 2);
            pv = *(float2*)&o;
            mv = *(float2*)&acc[q][j];
            mv.x += pv.x; mv.y += pv.y; *(float2*)&acc[q][j] = mv;
        }
        sumw[q] += __shfl_xor_sync(0xffffffffu, sumw[q], 1);
        sumw[q] += __shfl_xor_sync(0xffffffffu, sumw[q], 2);
    }

    if (ms == 0) {
#pragma unroll
        for (int q = 0; q < 4; q++) {
            float inv = (sumw[q] > 0.f) ? __fdividef(1.f, sumw[q]) : 0.f;
            float* dst = &g_hcat[(size_t)(bN + qbase + q) * 128 + (hh << 4)];
            float2 p0 = *(float2*)&acc[q][0], p1 = *(float2*)&acc[q][1];
            float2 p2 = *(float2*)&acc[q][2], p3 = *(float2*)&acc[q][3];
            float2 p4 = *(float2*)&acc[q][4], p5 = *(float2*)&acc[q][5];
            float2 p6 = *(float2*)&acc[q][6], p7 = *(float2*)&acc[q][7];
            *(float4*)(dst)      = make_float4(p0.x*inv, p0.y*inv, p1.x*inv, p1.y*inv);
            *(float4*)(dst + 4)  = make_float4(p2.x*inv, p2.y*inv, p3.x*inv, p3.y*inv);
            *(float4*)(dst + 8)  = make_float4(p4.x*inv, p4.y*inv, p5.x*inv, p5.y*inv);
            *(float4*)(dst + 12) = make_float4(p6.x*inv, p6.y*inv, p7.x*inv, p7.y*inv);
        }
    }
}

// ---------------- LN1: warp-per-row, float4, shuffle-only reduce ------------
__global__ __launch_bounds__(256) void ln_kernel(
        const float* __restrict__ A, const float* __restrict__ R,
        const float* __restrict__ g, const float* __restrict__ bta,
        float* __restrict__ out) {
    int wp = threadIdx.x >> 5, l = threadIdx.x & 31;
    int row = blockIdx.x * 8 + wp;
    size_t base = (size_t)row * Dd + (l << 2);
    float4 a4 = *(const float4*)&A[base];
    float4 r4 = *(const float4*)&R[base];
    float v[4] = {a4.x + r4.x, a4.y + r4.y, a4.z + r4.z, a4.w + r4.w};
    float s = v[0] + v[1] + v[2] + v[3];
    float s2 = v[0]*v[0] + v[1]*v[1] + v[2]*v[2] + v[3]*v[3];
#pragma unroll
    for (int o = 16; o > 0; o >>= 1) {
        s  += __shfl_xor_sync(0xffffffffu, s,  o);
        s2 += __shfl_xor_sync(0xffffffffu, s2, o);
    }
    float mu  = s * (1.f / Dd);
    float var = s2 * (1.f / Dd) - mu * mu;
    float rs = rsqrtf(var + EPSc);
    float4 g4 = *(const float4*)&g[l << 2];
    float4 b4 = *(const float4*)&bta[l << 2];
    float4 o4;
    o4.x = (v[0]-mu)*rs*g4.x + b4.x; o4.y = (v[1]-mu)*rs*g4.y + b4.y;
    o4.z = (v[2]-mu)*rs*g4.z + b4.z; o4.w = (v[3]-mu)*rs*g4.w + b4.w;
    *(float4*)&out[base] = o4;
}

// ---------------- launch ----------------------------------------------------
extern "C" void kernel_launch(void* const* d_in, const int* in_sizes, int n_in,
                              void* d_out, int out_size) {
    const float* h    = (const float*)d_in[0];
    const int*   adj  = (const int*)d_in[1];
    const float* W    = (const float*)d_in[2];
    const float* a    = (const float*)d_in[3];
    const float* ln1g = (const float*)d_in[4];
    const float* ln1b = (const float*)d_in[5];
    const float* w1   = (const float*)d_in[6];
    const float* b1   = (const float*)d_in[7];
    const float* w2   = (const float*)d_in[8];
    const float* b2   = (const float*)d_in[9];
    const float* ln2g = (const float*)d_in[10];
    const float* ln2b = (const float*)d_in[11];
    float* out = (float*)d_out;

    float *Wt, *Wh, *hcat, *x, *y;
    cudaGetSymbolAddress((void**)&Wt,   g_Wt);
    cudaGetSymbolAddress((void**)&Wh,   g_Wh);
    cudaGetSymbolAddress((void**)&hcat, g_hcat);
    cudaGetSymbolAddress((void**)&x,    g_x);
    cudaGetSymbolAddress((void**)&y,    g_y);

    // mask pack + W reorder (fused)
    prep_kernel<<<(Bb * Nn * Nn) / 1024, 256>>>((const int4*)adj, W);
    // Wh + score/exp tables (fused)
    gemm_kernel<0><<<dim3(1, ROWS / 64), 256>>>(h, Wt, nullptr, a, nullptr, nullptr,
                                                Wh, Dd, Dd);
    // attention
    att_kernel<<<dim3(Nn / 128, Hh, Bb), 128>>>();
    // LN1(hcat + h) -> x
    ln_kernel<<<ROWS / 8, 256>>>(hcat, h, ln1g, ln1b, x);
    // y = relu(x @ w1 + b1)
    gemm_kernel<1><<<dim3(2, ROWS / 64), 256>>>(x, w1, b1, nullptr, nullptr, nullptr,
                                                y, Dd, 2 * Dd);
    // out = LN2(x + y @ w2 + b2)
    gemm_kernel<2><<<dim3(1, ROWS / 64), 256>>>(y, w2, b2, x, ln2g, ln2b,
                                                out, 2 * Dd, Dd);
}

// round 11
// speedup vs baseline: 2.0418x; 1.1561x over previous
#include <cuda_runtime.h>
#include <cuda_bf16.h>
#include <cstdint>

#define Bb   8
#define Nn   1024
#define Hh   8
#define Dd   128
#define ROWS (Bb*Nn)      // 8192
#define EPSc 1e-5f

typedef unsigned long long ull;

// ---------------- scratch (static; no cudaMalloc) ---------------------------
__device__ float  g_Wt[Dd*Dd];
__device__ float  g_Wh[ROWS*Dd];
__device__ float4 g_q[Bb*Hh*Nn];   // {s_i, e^{s_i}, e^{0.2 s_i}, 0}
__device__ float4 g_k[Bb*Hh*Nn];
__device__ ull    g_maskbits[(size_t)ROWS*Nn/64];
__device__ float  g_hcat[ROWS*Dd];
__device__ float  g_x[ROWS*Dd];
__device__ float  g_y[ROWS*2*Dd];

// ---------------- helpers ---------------------------------------------------
__device__ __forceinline__ ull pack2(float x) {
    ull r;
    asm("mov.b64 %0, {%1, %1};" : "=l"(r) : "f"(x));
    return r;
}
__device__ __forceinline__ void fma2(ull& acc, ull ab, ull c) {
    asm("fma.rn.f32x2 %0, %1, %2, %0;" : "+l"(acc) : "l"(ab), "l"(c));
}
__device__ __forceinline__ unsigned cvt_tf32(float x) {
    unsigned r;
    asm("cvt.rna.tf32.f32 %0, %1;" : "=r"(r) : "f"(x));
    return r;
}
__device__ __forceinline__ void mma_tf32(float* d, const unsigned* a, const unsigned* b) {
    asm("mma.sync.aligned.m16n8k8.row.col.f32.tf32.tf32.f32 "
        "{%0,%1,%2,%3}, {%4,%5,%6,%7}, {%8,%9}, {%0,%1,%2,%3};"
        : "+f"(d[0]), "+f"(d[1]), "+f"(d[2]), "+f"(d[3])
        : "r"(a[0]), "r"(a[1]), "r"(a[2]), "r"(a[3]), "r"(b[0]), "r"(b[1]));
}
union F4U { float4 f4; ull u[2]; float f[4]; };

// ---------------- 1. pack mask bits + reorder W (fused) ---------------------
__global__ __launch_bounds__(256) void prep_kernel(const int4* __restrict__ adj4,
                                                   const float* __restrict__ W) {
    __shared__ unsigned char nib[256];
    int t = threadIdx.x;
    int4 v = adj4[(size_t)blockIdx.x * 256 + t];
    unsigned n = (v.x != 0) | ((v.y != 0) << 1) | ((v.z != 0) << 2) | ((v.w != 0) << 3);
    nib[t] = (unsigned char)n;
    if (blockIdx.x < 64) {
        int tid = blockIdx.x * 256 + t;      // < 16384
        int i = tid >> 7;
        int o = tid & 127;
        int hh = o >> 4, d = o & 15;
        g_Wt[tid] = W[(hh << 11) + (i << 4) + d];
    }
    __syncthreads();
    if (t < 16) {
        uint4 bytes = *(const uint4*)(nib + t * 16);
        unsigned w[4] = {bytes.x, bytes.y, bytes.z, bytes.w};
        ull word = 0;
#pragma unroll
        for (int i = 0; i < 4; i++) {
            unsigned x = w[i];
            unsigned o = (x & 0xFu) | ((x >> 4) & 0xF0u) |
                         ((x >> 8) & 0xF00u) | ((x >> 12) & 0xF000u);
            word |= (ull)o << (16 * i);
        }
        g_maskbits[(size_t)blockIdx.x * 16 + t] = word;
    }
}

// ---------------- fused 64x128-tile SGEMM (f32x2 core), 3 modes -------------
template<int MODE>
__global__ __launch_bounds__(256) void gemm_kernel(
        const float* __restrict__ A, const float* __restrict__ Bm,
        const float* __restrict__ bias, const float* __restrict__ extra,
        const float* __restrict__ gam, const float* __restrict__ bet,
        float* __restrict__ C, int K, int N) {
    __shared__ float As[16][68];
    __shared__ float Bs[16][128];
    __shared__ float sa_src[128], sa_dst[128];
    int t  = threadIdx.x;
    int tx = t & 15, ty = t >> 4;
    int row0 = blockIdx.y * 64;
    int col0 = blockIdx.x * 128;

    if (MODE == 0 && t < 128) {
        int hh = t >> 4, d = t & 15;
        sa_src[t] = extra[hh * 32 + d];
        sa_dst[t] = extra[hh * 32 + 16 + d];
    }

    ull acc2[4][4];
#pragma unroll
    for (int i = 0; i < 4; i++)
#pragma unroll
        for (int j = 0; j < 4; j++) acc2[i][j] = 0ULL;

    int arow = t >> 2, ak = (t & 3) << 2;
    for (int k0 = 0; k0 < K; k0 += 16) {
        float4 av = *(const float4*)&A[(size_t)(row0 + arow) * K + k0 + ak];
        int brow0 = t >> 5, bcol = (t & 31) << 2;
        float4 b0 = *(const float4*)&Bm[(size_t)(k0 + brow0) * N + col0 + bcol];
        float4 b1 = *(const float4*)&Bm[(size_t)(k0 + brow0 + 8) * N + col0 + bcol];
        __syncthreads();
        As[ak + 0][arow] = av.x; As[ak + 1][arow] = av.y;
        As[ak + 2][arow] = av.z; As[ak + 3][arow] = av.w;
        *(float4*)&Bs[brow0][bcol]     = b0;
        *(float4*)&Bs[brow0 + 8][bcol] = b1;
        __syncthreads();
#pragma unroll
        for (int k = 0; k < 16; k++) {
            float4 a4 = *(const float4*)&As[k][ty << 2];
            F4U q0, q1;
            q0.f4 = *(const float4*)&Bs[k][tx << 3];
            q1.f4 = *(const float4*)&Bs[k][(tx << 3) + 4];
            ull bp[4] = {q0.u[0], q0.u[1], q1.u[0], q1.u[1]};
            ull ap[4] = {pack2(a4.x), pack2(a4.y), pack2(a4.z), pack2(a4.w)};
#pragma unroll
            for (int i = 0; i < 4; i++)
#pragma unroll
                for (int j = 0; j < 4; j++) fma2(acc2[i][j], ap[i], bp[j]);
        }
    }

    float acc[4][8];
#pragma unroll
    for (int i = 0; i < 4; i++)
#pragma unroll
        for (int j = 0; j < 4; j++) {
            float2 p = *(float2*)&acc2[i][j];
            acc[i][2 * j]     = p.x;
            acc[i][2 * j + 1] = p.y;
        }

    if (MODE == 0) {
#pragma unroll
        for (int i = 0; i < 4; i++) {
            int r = row0 + (ty << 2) + i;
            *(float4*)&C[(size_t)r * 128 + (tx << 3)] =
                make_float4(acc[i][0], acc[i][1], acc[i][2], acc[i][3]);
            *(float4*)&C[(size_t)r * 128 + (tx << 3) + 4] =
                make_float4(acc[i][4], acc[i][5], acc[i][6], acc[i][7]);
            float sp = 0.f, dp = 0.f;
#pragma unroll
            for (int j = 0; j < 8; j++) {
                sp += acc[i][j] * sa_src[(tx << 3) + j];
                dp += acc[i][j] * sa_dst[(tx << 3) + j];
            }
            sp += __shfl_xor_sync(0xffffffffu, sp, 1);
            dp += __shfl_xor_sync(0xffffffffu, dp, 1);
            if (!(tx & 1)) {
                int b = r >> 10, n = r & 1023;
                int hh = tx >> 1;
                int idx = ((b << 3) + hh) * 1024 + n;
                g_q[idx] = make_float4(sp, __expf(sp), __expf(0.2f * sp), 0.f);
                g_k[idx] = make_float4(dp, __expf(dp), __expf(0.2f * dp), 0.f);
            }
        }
    } else if (MODE == 1) {
        float bv[8];
#pragma unroll
        for (int j = 0; j < 8; j++) bv[j] = bias[col0 + (tx << 3) + j];
#pragma unroll
        for (int i = 0; i < 4; i++) {
            int r = row0 + (ty << 2) + i;
            float4 r0, r1;
            r0.x = fmaxf(acc[i][0] + bv[0], 0.f); r0.y = fmaxf(acc[i][1] + bv[1], 0.f);
            r0.z = fmaxf(acc[i][2] + bv[2], 0.f); r0.w = fmaxf(acc[i][3] + bv[3], 0.f);
            r1.x = fmaxf(acc[i][4] + bv[4], 0.f); r1.y = fmaxf(acc[i][5] + bv[5], 0.f);
            r1.z = fmaxf(acc[i][6] + bv[6], 0.f); r1.w = fmaxf(acc[i][7] + bv[7], 0.f);
            *(float4*)&C[(size_t)r * N + col0 + (tx << 3)]     = r0;
            *(float4*)&C[(size_t)r * N + col0 + (tx << 3) + 4] = r1;
        }
    } else {
        float bv[8], gv[8], bb[8];
#pragma unroll
        for (int j = 0; j < 8; j++) {
            bv[j] = bias[(tx << 3) + j];
            gv[j] = gam[(tx << 3) + j];
            bb[j] = bet[(tx << 3) + j];
        }
#pragma unroll
        for (int i = 0; i < 4; i++) {
            int r = row0 + (ty << 2) + i;
            float4 x0 = *(const float4*)&extra[(size_t)r * 128 + (tx << 3)];
            float4 x1 = *(const float4*)&extra[(size_t)r * 128 + (tx << 3) + 4];
            float v[8] = {x0.x, x0.y, x0.z, x0.w, x1.x, x1.y, x1.z, x1.w};
            float s = 0.f, s2 = 0.f;
#pragma unroll
            for (int j = 0; j < 8; j++) {
                v[j] += acc[i][j] + bv[j];
                s += v[j]; s2 += v[j] * v[j];
            }
#pragma unroll
            for (int o = 1; o <= 8; o <<= 1) {
                s  += __shfl_xor_sync(0xffffffffu, s,  o);
                s2 += __shfl_xor_sync(0xffffffffu, s2, o);
            }
            float mu  = s * (1.f / 128.f);
            float var = s2 * (1.f / 128.f) - mu * mu;
            float rs  = rsqrtf(var + EPSc);
            float4 r0, r1;
            r0.x = (v[0]-mu)*rs*gv[0]+bb[0]; r0.y = (v[1]-mu)*rs*gv[1]+bb[1];
            r0.z = (v[2]-mu)*rs*gv[2]+bb[2]; r0.w = (v[3]-mu)*rs*gv[3]+bb[3];
            r1.x = (v[4]-mu)*rs*gv[4]+bb[4]; r1.y = (v[5]-mu)*rs*gv[5]+bb[5];
            r1.z = (v[6]-mu)*rs*gv[6]+bb[6]; r1.w = (v[7]-mu)*rs*gv[7]+bb[7];
            *(float4*)&C[(size_t)r * 128 + (tx << 3)]     = r0;
            *(float4*)&C[(size_t)r * 128 + (tx << 3) + 4] = r1;
        }
    }
}

// ---------------- tensor-core masked-softmax attention ----------------------
// grid (8, H, B), 128 threads = 4 warps. Warp handles 32 queries (2 m16 tiles).
// P(128q x 128k) built per key-tile DIRECTLY in mma A-fragment layout (tf32);
// V = Wh head-slice (128k x 16) + ones column at col 16 -> MMA yields sumw free.
// weight = max(e^{si}*e^{sj}, e^{0.2si}*e^{0.2sj}), masked to 0 via bit test.
__global__ __launch_bounds__(128, 4) void att_kernel() {
    __shared__ unsigned sV[128 * 24];   // tf32 V tile, stride 24 (12 KB)
    __shared__ float2   skp[128];       // {e^sj, e^0.2sj}
    int b = blockIdx.z, hh = blockIdx.y;
    int t = threadIdx.x, l = t & 31, wp = t >> 5;
    int g = l >> 2, tig = l & 3;
    int bN = b * Nn, bhN = (b * Hh + hh) * Nn;
    int qbase = blockIdx.x * 128 + wp * 32;

    int qq[4] = {qbase + g, qbase + g + 8, qbase + g + 16, qbase + g + 24};
    float E1[4], E2[4];
    size_t mro[4];
#pragma unroll
    for (int q = 0; q < 4; q++) {
        float4 v = g_q[bhN + qq[q]];
        E1[q] = v.y; E2[q] = v.z;
        mro[q] = (size_t)(bN + qq[q]) * 16;
    }
    unsigned bitA = 1u << tig, bitB = 1u << (tig + 4);

    float d[2][3][4];
#pragma unroll
    for (int mt = 0; mt < 2; mt++)
#pragma unroll
        for (int n = 0; n < 3; n++)
#pragma unroll
            for (int c = 0; c < 4; c++) d[mt][n][c] = 0.f;

    for (int kt = 0; kt < 8; kt++) {
        __syncthreads();
        {   // stage V + kp: thread t owns key row kt*128 + t
            int key = kt * 128 + t;
            const float4* wr = (const float4*)&g_Wh[(size_t)(bN + key) * 128 + (hh << 4)];
            float4 v0 = wr[0], v1 = wr[1], v2 = wr[2], v3 = wr[3];
            unsigned* dst = &sV[t * 24];
            *(uint4*)&dst[0]  = make_uint4(cvt_tf32(v0.x), cvt_tf32(v0.y), cvt_tf32(v0.z), cvt_tf32(v0.w));
            *(uint4*)&dst[4]  = make_uint4(cvt_tf32(v1.x), cvt_tf32(v1.y), cvt_tf32(v1.z), cvt_tf32(v1.w));
            *(uint4*)&dst[8]  = make_uint4(cvt_tf32(v2.x), cvt_tf32(v2.y), cvt_tf32(v2.z), cvt_tf32(v2.w));
            *(uint4*)&dst[12] = make_uint4(cvt_tf32(v3.x), cvt_tf32(v3.y), cvt_tf32(v3.z), cvt_tf32(v3.w));
            *(uint4*)&dst[16] = make_uint4(0x3f800000u, 0u, 0u, 0u);   // ones col + zeros
            *(uint4*)&dst[20] = make_uint4(0u, 0u, 0u, 0u);
            float4 kv = g_k[bhN + key];
            skp[t] = make_float2(kv.y, kv.z);
        }
        __syncthreads();

#pragma unroll
        for (int half = 0; half < 2; half++) {
            ull cur[4];
#pragma unroll
            for (int q = 0; q < 4; q++) cur[q] = g_maskbits[mro[q] + 2 * kt + half];
#pragma unroll
            for (int ks = 0; ks < 8; ks++) {
                int krow = half * 64 + ks * 8;
                unsigned bfr[3][2];
#pragma unroll
                for (int n = 0; n < 3; n++) {
                    bfr[n][0] = sV[(krow + tig) * 24 + n * 8 + g];
                    bfr[n][1] = sV[(krow + tig + 4) * 24 + n * 8 + g];
                }
                float2 kp0 = skp[krow + tig];
                float2 kp1 = skp[krow + tig + 4];
#pragma unroll
                for (int mt = 0; mt < 2; mt++) {
                    unsigned c0 = (unsigned)cur[2 * mt];
                    unsigned c1 = (unsigned)cur[2 * mt + 1];
                    float w00 = fmaxf(E1[2*mt]   * kp0.x, E2[2*mt]   * kp0.y);
                    float w10 = fmaxf(E1[2*mt+1] * kp0.x, E2[2*mt+1] * kp0.y);
                    float w01 = fmaxf(E1[2*mt]   * kp1.x, E2[2*mt]   * kp1.y);
                    float w11 = fmaxf(E1[2*mt+1] * kp1.x, E2[2*mt+1] * kp1.y);
                    w00 = (c0 & bitA) ? w00 : 0.f;
                    w10 = (c1 & bitA) ? w10 : 0.f;
                    w01 = (c0 & bitB) ? w01 : 0.f;
                    w11 = (c1 & bitB) ? w11 : 0.f;
                    unsigned a[4] = {cvt_tf32(w00), cvt_tf32(w10),
                                     cvt_tf32(w01), cvt_tf32(w11)};
                    mma_tf32(d[mt][0], a, bfr[0]);
                    mma_tf32(d[mt][1], a, bfr[1]);
                    mma_tf32(d[mt][2], a, bfr[2]);
                }
#pragma unroll
                for (int q = 0; q < 4; q++) cur[q] >>= 8;
            }
        }
    }

    // epilogue: sumw is D column 16 (ntile2, local col 0 -> tig==0 lanes)
#pragma unroll
    for (int mt = 0; mt < 2; mt++) {
        float sw0 = __shfl_sync(0xffffffffu, d[mt][2][0], l & ~3);
        float sw1 = __shfl_sync(0xffffffffu, d[mt][2][2], l & ~3);
        float inv0 = (sw0 > 0.f) ? __fdividef(1.f, sw0) : 0.f;
        float inv1 = (sw1 > 0.f) ? __fdividef(1.f, sw1) : 0.f;
        float* r0 = &g_hcat[(size_t)(bN + qq[2*mt])     * 128 + (hh << 4)];
        float* r1 = &g_hcat[(size_t)(bN + qq[2*mt + 1]) * 128 + (hh << 4)];
        *(float2*)&r0[2*tig]     = make_float2(d[mt][0][0] * inv0, d[mt][0][1] * inv0);
        *(float2*)&r0[8 + 2*tig] = make_float2(d[mt][1][0] * inv0, d[mt][1][1] * inv0);
        *(float2*)&r1[2*tig]     = make_float2(d[mt][0][2] * inv1, d[mt][0][3] * inv1);
        *(float2*)&r1[8 + 2*tig] = make_float2(d[mt][1][2] * inv1, d[mt][1][3] * inv1);
    }
}

// ---------------- LN1: warp-per-row, float4, shuffle-only reduce ------------
__global__ __launch_bounds__(256) void ln_kernel(
        const float* __restrict__ A, const float* __restrict__ R,
        const float* __restrict__ g, const float* __restrict__ bta,
        float* __restrict__ out) {
    int wp = threadIdx.x >> 5, l = threadIdx.x & 31;
    int row = blockIdx.x * 8 + wp;
    size_t base = (size_t)row * Dd + (l << 2);
    float4 a4 = *(const float4*)&A[base];
    float4 r4 = *(const float4*)&R[base];
    float v[4] = {a4.x + r4.x, a4.y + r4.y, a4.z + r4.z, a4.w + r4.w};
    float s = v[0] + v[1] + v[2] + v[3];
    float s2 = v[0]*v[0] + v[1]*v[1] + v[2]*v[2] + v[3]*v[3];
#pragma unroll
    for (int o = 16; o > 0; o >>= 1) {
        s  += __shfl_xor_sync(0xffffffffu, s,  o);
        s2 += __shfl_xor_sync(0xffffffffu, s2, o);
    }
    float mu  = s * (1.f / Dd);
    float var = s2 * (1.f / Dd) - mu * mu;
    float rs = rsqrtf(var + EPSc);
    float4 g4 = *(const float4*)&g[l << 2];
    float4 b4 = *(const float4*)&bta[l << 2];
    float4 o4;
    o4.x = (v[0]-mu)*rs*g4.x + b4.x; o4.y = (v[1]-mu)*rs*g4.y + b4.y;
    o4.z = (v[2]-mu)*rs*g4.z + b4.z; o4.w = (v[3]-mu)*rs*g4.w + b4.w;
    *(float4*)&out[base] = o4;
}

// ---------------- launch ----------------------------------------------------
extern "C" void kernel_launch(void* const* d_in, const int* in_sizes, int n_in,
                              void* d_out, int out_size) {
    const float* h    = (const float*)d_in[0];
    const int*   adj  = (const int*)d_in[1];
    const float* W    = (const float*)d_in[2];
    const float* a    = (const float*)d_in[3];
    const float* ln1g = (const float*)d_in[4];
    const float* ln1b = (const float*)d_in[5];
    const float* w1   = (const float*)d_in[6];
    const float* b1   = (const float*)d_in[7];
    const float* w2   = (const float*)d_in[8];
    const float* b2   = (const float*)d_in[9];
    const float* ln2g = (const float*)d_in[10];
    const float* ln2b = (const float*)d_in[11];
    float* out = (float*)d_out;

    float *Wt, *Wh, *hcat, *x, *y;
    cudaGetSymbolAddress((void**)&Wt,   g_Wt);
    cudaGetSymbolAddress((void**)&Wh,   g_Wh);
    cudaGetSymbolAddress((void**)&hcat, g_hcat);
    cudaGetSymbolAddress((void**)&x,    g_x);
    cudaGetSymbolAddress((void**)&y,    g_y);

    // mask pack + W reorder (fused)
    prep_kernel<<<(Bb * Nn * Nn) / 1024, 256>>>((const int4*)adj, W);
    // Wh + score/exp tables (fused)
    gemm_kernel<0><<<dim3(1, ROWS / 64), 256>>>(h, Wt, nullptr, a, nullptr, nullptr,
                                                Wh, Dd, Dd);
    // attention (tensor-core)
    att_kernel<<<dim3(Nn / 128, Hh, Bb), 128>>>();
    // LN1(hcat + h) -> x
    ln_kernel<<<ROWS / 8, 256>>>(hcat, h, ln1g, ln1b, x);
    // y = relu(x @ w1 + b1)
    gemm_kernel<1><<<dim3(2, ROWS / 64), 256>>>(x, w1, b1, nullptr, nullptr, nullptr,
                                                y, Dd, 2 * Dd);
    // out = LN2(x + y @ w2 + b2)
    gemm_kernel<2><<<dim3(1, ROWS / 64), 256>>>(y, w2, b2, x, ln2g, ln2b,
                                                out, 2 * Dd, Dd);
}